// round 5
// baseline (speedup 1.0000x reference)
#include <cuda_runtime.h>

#define BATCH   64
#define D_IN    512
#define D_OUT   512
#define GRID_N  100
#define LN_EPS   1e-5f
#define GRID_EPS 1e-6f

#define OBLK     128                 // o's per CTA
#define NOBLK    (D_OUT / OBLK)      // 4
#define ICHUNK   2                   // i's per CTA
#define NCHUNKS  (D_IN / ICHUNK)     // 256

#define ISTRIDE  (D_OUT * GRID_N * 4)   // 204800 floats per i
#define OSTRIDE  (GRID_N * 4)           // 400 floats per o

#define WAVE 8

// ---- scratch (__device__ globals; no allocations allowed) ----
__device__ int        g_idx_s[BATCH * D_IN];
__device__ float4     g_w_s[BATCH * D_IN];
__device__ ulonglong2 g_ug[D_IN * BATCH];   // per i: up to 64 {mask, gcell}
__device__ int        g_ug_cnt[D_IN];
__device__ float      g_partial[NCHUNKS * BATCH * D_OUT];   // 33.5 MB

// ---------------------------------------------------------------------------
// Kernel 1: LayerNorm + grid index + Bernstein basis weights.
// ---------------------------------------------------------------------------
__global__ __launch_bounds__(128) void prep_kernel(
    const float* __restrict__ x,
    const float* __restrict__ ln_w,
    const float* __restrict__ ln_b,
    const float* __restrict__ M)
{
    const int b = blockIdx.x;
    const int t = threadIdx.x;

    __shared__ float red1[4], red2[4];
    __shared__ float sM[16];
    if (t < 16) sM[t] = M[t];

    const float4 v = reinterpret_cast<const float4*>(x + b * D_IN)[t];

    float s1 = v.x + v.y + v.z + v.w;
    float s2 = v.x * v.x + v.y * v.y + v.z * v.z + v.w * v.w;
    #pragma unroll
    for (int off = 16; off > 0; off >>= 1) {
        s1 += __shfl_xor_sync(0xffffffffu, s1, off);
        s2 += __shfl_xor_sync(0xffffffffu, s2, off);
    }
    if ((t & 31) == 0) { red1[t >> 5] = s1; red2[t >> 5] = s2; }
    __syncthreads();
    if (t < 32) {
        float r1 = (t < 4) ? red1[t] : 0.0f;
        float r2 = (t < 4) ? red2[t] : 0.0f;
        #pragma unroll
        for (int off = 2; off > 0; off >>= 1) {
            r1 += __shfl_xor_sync(0xffffffffu, r1, off);
            r2 += __shfl_xor_sync(0xffffffffu, r2, off);
        }
        if (t == 0) { red1[0] = r1; red2[0] = r2; }
    }
    __syncthreads();

    const float mean = red1[0] * (1.0f / D_IN);
    const float var  = red2[0] * (1.0f / D_IN) - mean * mean;
    const float rstd = rsqrtf(var + LN_EPS);

    const float4 lw = reinterpret_cast<const float4*>(ln_w)[t];
    const float4 lb = reinterpret_cast<const float4*>(ln_b)[t];

    const float vv[4] = { v.x, v.y, v.z, v.w };
    const float ww[4] = { lw.x, lw.y, lw.z, lw.w };
    const float bb[4] = { lb.x, lb.y, lb.z, lb.w };

    #pragma unroll
    for (int j = 0; j < 4; j++) {
        const int i = t * 4 + j;
        float xn = (vv[j] - mean) * rstd * ww[j] + bb[j];
        xn = fminf(fmaxf(xn, -1.0f + GRID_EPS), 1.0f - GRID_EPS);
        xn = (xn + 1.0f) * 0.5f;
        const float scaled = xn * (float)GRID_N;
        int gi = (int)floorf(scaled);
        gi = max(0, min(gi, GRID_N - 1));
        const float tt  = scaled - (float)gi;
        const float tt2 = tt * tt;
        const float tt3 = tt2 * tt;

        float4 w;
        w.x = sM[0] + tt * sM[4] + tt2 * sM[8]  + tt3 * sM[12];
        w.y = sM[1] + tt * sM[5] + tt2 * sM[9]  + tt3 * sM[13];
        w.z = sM[2] + tt * sM[6] + tt2 * sM[10] + tt3 * sM[14];
        w.w = sM[3] + tt * sM[7] + tt2 * sM[11] + tt3 * sM[15];

        g_idx_s[b * D_IN + i] = gi;
        g_w_s  [b * D_IN + i] = w;
    }
}

// ---------------------------------------------------------------------------
// Kernel 2: per-i unique grid cells + batch masks (deterministic order).
// ---------------------------------------------------------------------------
__global__ __launch_bounds__(64) void build_unique_kernel()
{
    const int i = blockIdx.x;
    const int b = threadIdx.x;

    __shared__ unsigned long long cm[GRID_N];
    for (int c = b; c < GRID_N; c += 64) cm[c] = 0ull;
    __syncthreads();

    const int g = g_idx_s[b * D_IN + i];
    atomicOr(&cm[g], 1ull << b);
    __syncthreads();

    if (b == 0) {
        int cnt = 0;
        ulonglong2* dst = &g_ug[i * BATCH];
        #pragma unroll 4
        for (int c = 0; c < GRID_N; c++) {
            const unsigned long long m = cm[c];
            if (m) {
                ulonglong2 e; e.x = m; e.y = (unsigned long long)c;
                dst[cnt++] = e;
            }
        }
        g_ug_cnt[i] = cnt;
    }
}

// ---------------------------------------------------------------------------
// Kernel 3: deduplicated gather, high occupancy (24 warps/SM), wave-of-8 MLP.
// grid = (NOBLK=4, NCHUNKS=256), 128 threads (one per o in block).
// ---------------------------------------------------------------------------
__global__ __launch_bounds__(128) void gather_kernel(const float* __restrict__ poly)
{
    const int tid   = threadIdx.x;
    const int o     = blockIdx.x * OBLK + tid;
    const int chunk = blockIdx.y;
    const int i0    = chunk * ICHUNK;

    __shared__ float      acc_s[BATCH][OBLK];       // 32 KB
    __shared__ float4     w_s[ICHUNK][BATCH];       // 2 KB
    __shared__ ulonglong2 ug_s[ICHUNK][BATCH];      // 2 KB
    __shared__ int        cnt_s[ICHUNK];

    #pragma unroll
    for (int b = 0; b < BATCH; b++) acc_s[b][tid] = 0.0f;

    // stage weights + unique lists (128 threads cover ICHUNK*BATCH = 128)
    {
        const int ii = tid >> 6;
        const int b  = tid & 63;
        w_s[ii][b]  = g_w_s[b * D_IN + i0 + ii];
        ug_s[ii][b] = g_ug[(i0 + ii) * BATCH + b];
        if (tid < ICHUNK) cnt_s[tid] = g_ug_cnt[i0 + tid];
    }
    __syncthreads();

    #pragma unroll
    for (int ii = 0; ii < ICHUNK; ii++) {
        const int cnt = cnt_s[ii];
        const float* pb = poly + (size_t)(i0 + ii) * ISTRIDE + (size_t)o * OSTRIDE;

        for (int j0 = 0; j0 < cnt; j0 += WAVE) {
            const int n = min(WAVE, cnt - j0);

            // ---- load wave: up to 8 independent gathers in flight ----
            float4 pv[WAVE];
            #pragma unroll
            for (int jj = 0; jj < WAVE; jj++) {
                if (jj < n) {
                    const int gc = (int)ug_s[ii][j0 + jj].y;
                    pv[jj] = *reinterpret_cast<const float4*>(pb + gc * 4);
                }
            }

            // ---- scatter wave (mask warp-uniform: no divergence) ----
            #pragma unroll
            for (int jj = 0; jj < WAVE; jj++) {
                if (jj < n) {
                    unsigned long long m = ug_s[ii][j0 + jj].x;
                    const float4 cur = pv[jj];
                    while (m) {
                        const int b = __ffsll((long long)m) - 1;
                        m &= m - 1;
                        const float4 w = w_s[ii][b];
                        acc_s[b][tid] += w.x * cur.x + w.y * cur.y
                                       + w.z * cur.z + w.w * cur.w;
                    }
                }
            }
        }
    }

    float* pp = g_partial + ((size_t)chunk * BATCH) * D_OUT + o;
    #pragma unroll
    for (int b = 0; b < BATCH; b++) pp[(size_t)b * D_OUT] = acc_s[b][tid];
}

// ---------------------------------------------------------------------------
// Kernel 4: reduce partials over 256 chunks.
// grid = (4 o-blocks, 64 batches), 128 threads; coalesced 128B warp-loads.
// ---------------------------------------------------------------------------
__global__ __launch_bounds__(128) void reduce_kernel(float* __restrict__ out)
{
    const int o = blockIdx.x * 128 + threadIdx.x;
    const int b = blockIdx.y;
    const float* p = g_partial + (size_t)b * D_OUT + o;

    float acc = 0.0f;
    #pragma unroll 16
    for (int c = 0; c < NCHUNKS; c++)
        acc += p[(size_t)c * (BATCH * D_OUT)];
    out[b * D_OUT + o] = acc;
}

// ---------------------------------------------------------------------------
extern "C" void kernel_launch(void* const* d_in, const int* in_sizes, int n_in,
                              void* d_out, int out_size)
{
    const float* x    = (const float*)d_in[0];   // (64, 512)
    const float* poly = (const float*)d_in[1];   // (512, 512, 100, 4)
    const float* ln_w = (const float*)d_in[2];   // (512,)
    const float* ln_b = (const float*)d_in[3];   // (512,)
    const float* M    = (const float*)d_in[4];   // (4, 4)
    float* out = (float*)d_out;                  // (64, 512) fp32

    prep_kernel<<<BATCH, 128>>>(x, ln_w, ln_b, M);
    build_unique_kernel<<<D_IN, 64>>>();
    gather_kernel<<<dim3(NOBLK, NCHUNKS), OBLK>>>(poly);
    reduce_kernel<<<dim3(NOBLK, BATCH), OBLK>>>(out);
}

// round 6
// speedup vs baseline: 2.3872x; 2.3872x over previous
#include <cuda_runtime.h>

#define BATCH   64
#define D_IN    512
#define D_OUT   512
#define GRID_N  100
#define NCHUNK  8
#define CHUNK   (D_IN / NCHUNK)   // 64
#define LN_EPS   1e-5f
#define GRID_EPS 1e-6f

#define ISTRIDE  (D_OUT * GRID_N * 4)   // 204800 floats per i
#define OSTRIDE  (GRID_N * 4)           // 400 floats per o

// ---- scratch (__device__ globals; no allocations allowed) ----
__device__ int    g_idx_s[BATCH * D_IN];
__device__ float4 g_w_s[BATCH * D_IN];
__device__ float  g_partial[NCHUNK * BATCH * D_OUT];   // 8.4 MB

// ---------------------------------------------------------------------------
// Kernel 1: LayerNorm + grid index + Bernstein basis weights.
// One CTA per batch, 128 threads, float4 per thread, fused mean/var reduce.
// ---------------------------------------------------------------------------
__global__ __launch_bounds__(128) void prep_kernel(
    const float* __restrict__ x,
    const float* __restrict__ ln_w,
    const float* __restrict__ ln_b,
    const float* __restrict__ M)
{
    const int b = blockIdx.x;
    const int t = threadIdx.x;

    __shared__ float red1[4], red2[4];
    __shared__ float sM[16];
    if (t < 16) sM[t] = M[t];

    const float4 v = reinterpret_cast<const float4*>(x + b * D_IN)[t];

    float s1 = v.x + v.y + v.z + v.w;
    float s2 = v.x * v.x + v.y * v.y + v.z * v.z + v.w * v.w;
    #pragma unroll
    for (int off = 16; off > 0; off >>= 1) {
        s1 += __shfl_xor_sync(0xffffffffu, s1, off);
        s2 += __shfl_xor_sync(0xffffffffu, s2, off);
    }
    if ((t & 31) == 0) { red1[t >> 5] = s1; red2[t >> 5] = s2; }
    __syncthreads();
    if (t < 32) {
        float r1 = (t < 4) ? red1[t] : 0.0f;
        float r2 = (t < 4) ? red2[t] : 0.0f;
        #pragma unroll
        for (int off = 2; off > 0; off >>= 1) {
            r1 += __shfl_xor_sync(0xffffffffu, r1, off);
            r2 += __shfl_xor_sync(0xffffffffu, r2, off);
        }
        if (t == 0) { red1[0] = r1; red2[0] = r2; }
    }
    __syncthreads();

    const float mean = red1[0] * (1.0f / D_IN);
    const float var  = red2[0] * (1.0f / D_IN) - mean * mean;
    const float rstd = rsqrtf(var + LN_EPS);

    const float4 lw = reinterpret_cast<const float4*>(ln_w)[t];
    const float4 lb = reinterpret_cast<const float4*>(ln_b)[t];

    const float vv[4] = { v.x, v.y, v.z, v.w };
    const float ww[4] = { lw.x, lw.y, lw.z, lw.w };
    const float bb[4] = { lb.x, lb.y, lb.z, lb.w };

    #pragma unroll
    for (int j = 0; j < 4; j++) {
        const int i = t * 4 + j;
        float xn = (vv[j] - mean) * rstd * ww[j] + bb[j];
        xn = fminf(fmaxf(xn, -1.0f + GRID_EPS), 1.0f - GRID_EPS);
        xn = (xn + 1.0f) * 0.5f;
        const float scaled = xn * (float)GRID_N;
        int gi = (int)floorf(scaled);
        gi = max(0, min(gi, GRID_N - 1));
        const float tt  = scaled - (float)gi;
        const float tt2 = tt * tt;
        const float tt3 = tt2 * tt;

        float4 w;
        w.x = sM[0] + tt * sM[4] + tt2 * sM[8]  + tt3 * sM[12];
        w.y = sM[1] + tt * sM[5] + tt2 * sM[9]  + tt3 * sM[13];
        w.z = sM[2] + tt * sM[6] + tt2 * sM[10] + tt3 * sM[14];
        w.w = sM[3] + tt * sM[7] + tt2 * sM[11] + tt3 * sM[15];

        g_idx_s[b * D_IN + i] = gi;
        g_w_s  [b * D_IN + i] = w;
    }
}

// ---------------------------------------------------------------------------
// Kernel 2: gather + dot4 accumulation (proven R2 structure: register acc,
// 56 warps/SM, unroll-8 MLP). grid = (BATCH, NCHUNK), 512 threads (thread=o).
// blockIdx.x = b (fast) so all batches of an i-chunk co-run -> L2 reuse.
// ---------------------------------------------------------------------------
__global__ __launch_bounds__(512) void gather_kernel(const float* __restrict__ poly)
{
    const int b     = blockIdx.x;
    const int chunk = blockIdx.y;
    const int o     = threadIdx.x;

    __shared__ int    sg[CHUNK];
    __shared__ float4 sw[CHUNK];
    const int base = b * D_IN + chunk * CHUNK;
    if (o < CHUNK) {
        sg[o] = g_idx_s[base + o];
        sw[o] = g_w_s  [base + o];
    }
    __syncthreads();

    const float* pbase = poly
        + (size_t)(chunk * CHUNK) * (size_t)ISTRIDE
        + (size_t)o * OSTRIDE;

    float acc = 0.0f;
    #pragma unroll 8
    for (int ii = 0; ii < CHUNK; ii++) {
        const int    gi = sg[ii];
        const float4 w  = sw[ii];
        const float4 pv = *reinterpret_cast<const float4*>(
            pbase + (size_t)ii * (size_t)ISTRIDE + gi * 4);
        acc += w.x * pv.x + w.y * pv.y + w.z * pv.z + w.w * pv.w;
    }

    g_partial[(chunk * BATCH + b) * D_OUT + o] = acc;
}

// ---------------------------------------------------------------------------
// Kernel 3: reduce partials over 8 chunks. float4, 8 independent loads per
// thread (MLP=8). 64 CTAs x 128 threads = 8192 threads (one per float4 out).
// ---------------------------------------------------------------------------
__global__ __launch_bounds__(128) void reduce_kernel(float* __restrict__ out)
{
    const int idx4 = blockIdx.x * 128 + threadIdx.x;     // 0..8191
    const float4* p = reinterpret_cast<const float4*>(g_partial) + idx4;

    float4 v[NCHUNK];
    #pragma unroll
    for (int c = 0; c < NCHUNK; c++)
        v[c] = p[(size_t)c * (BATCH * D_OUT / 4)];

    float4 acc;
    acc.x = ((v[0].x + v[1].x) + (v[2].x + v[3].x)) + ((v[4].x + v[5].x) + (v[6].x + v[7].x));
    acc.y = ((v[0].y + v[1].y) + (v[2].y + v[3].y)) + ((v[4].y + v[5].y) + (v[6].y + v[7].y));
    acc.z = ((v[0].z + v[1].z) + (v[2].z + v[3].z)) + ((v[4].z + v[5].z) + (v[6].z + v[7].z));
    acc.w = ((v[0].w + v[1].w) + (v[2].w + v[3].w)) + ((v[4].w + v[5].w) + (v[6].w + v[7].w));

    reinterpret_cast<float4*>(out)[idx4] = acc;
}

// ---------------------------------------------------------------------------
extern "C" void kernel_launch(void* const* d_in, const int* in_sizes, int n_in,
                              void* d_out, int out_size)
{
    const float* x    = (const float*)d_in[0];   // (64, 512)
    const float* poly = (const float*)d_in[1];   // (512, 512, 100, 4)
    const float* ln_w = (const float*)d_in[2];   // (512,)
    const float* ln_b = (const float*)d_in[3];   // (512,)
    const float* M    = (const float*)d_in[4];   // (4, 4)
    float* out = (float*)d_out;                  // (64, 512) fp32

    prep_kernel<<<BATCH, 128>>>(x, ln_w, ln_b, M);
    gather_kernel<<<dim3(BATCH, NCHUNK), D_OUT>>>(poly);
    reduce_kernel<<<(BATCH * D_OUT / 4) / 128, 128>>>(out);
}